// round 5
// baseline (speedup 1.0000x reference)
#include <cuda_runtime.h>

// GAE: advantages/targets, B=4096 rows, T=8192 timesteps.
// delta_t = r_t + GAMMA * v_{t+1} - v_t
// A_t = delta_t + COEF * A_{t+1}   (reverse scan, COEF = GAMMA*LAMBDA)
// targets_t = v_t + A_t
// Output layout: [advantages (B*T) | targets (B*T)] float32.
//
// R5: fully 16B-vectorized memory phases. values rows are misaligned by
// O = row%4 floats; templated phases make the realignment window select
// compile-time (switch over 4 instantiations). 1024 thr/CTA, 2 CTAs/SM
// (64 warps), 33KB smem (D only) -> big L1D carveout so phase-5 v re-read
// hits L1. Shuffle-based two-level affine scan.

constexpr int   B_CONST  = 4096;
constexpr int   T_CONST  = 8192;
constexpr float GAMMA    = 0.99f;
constexpr float COEF     = 0.99f * 0.95f;           // gamma * lambda
constexpr int   THREADS  = 1024;
constexpr int   NWARP    = THREADS / 32;            // 32
constexpr int   SEG      = T_CONST / THREADS;       // 8 elements per thread
constexpr int   NGRP     = T_CONST / (4 * THREADS); // 2 float4 groups/thread
constexpr int   TPAD     = T_CONST + T_CONST / 32;  // +1 pad float per 32

__device__ __forceinline__ int padi(int t) { return t + (t >> 5); }

// Phase 1: delta into padded smem. v loaded as two aligned float4s per group,
// realigned by compile-time O. r loaded as one aligned float4.
template<int O>
__device__ __forceinline__ void phase1(const float* __restrict__ r,
                                       const float* __restrict__ v,
                                       float* __restrict__ D, int tid)
{
    #pragma unroll
    for (int i = 0; i < NGRP; ++i) {
        int t4 = 4 * (tid + i * THREADS);
        float w0, w1, w2, w3, w4;                   // v[t4 .. t4+4]
        if (t4 == 0 || t4 == T_CONST - 4) {         // edge: stay in-bounds
            w0 = __ldg(v + t4);     w1 = __ldg(v + t4 + 1);
            w2 = __ldg(v + t4 + 2); w3 = __ldg(v + t4 + 3);
            w4 = __ldg(v + t4 + 4);
        } else {
            float4 lo = __ldg(reinterpret_cast<const float4*>(v + t4 - O));
            float4 hi = __ldg(reinterpret_cast<const float4*>(v + t4 - O + 4));
            float w[8] = {lo.x, lo.y, lo.z, lo.w, hi.x, hi.y, hi.z, hi.w};
            w0 = w[O]; w1 = w[O + 1]; w2 = w[O + 2]; w3 = w[O + 3]; w4 = w[O + 4];
        }
        float4 r4 = __ldg(reinterpret_cast<const float4*>(r + t4));
        int p = padi(t4);                           // p..p+3 contiguous, conflict-free
        D[p]     = r4.x + GAMMA * w1 - w0;
        D[p + 1] = r4.y + GAMMA * w2 - w1;
        D[p + 2] = r4.z + GAMMA * w3 - w2;
        D[p + 3] = r4.w + GAMMA * w4 - w3;
    }
}

// Phase 5: advantages from smem, v re-read (L1-resident), float4 stores.
template<int O>
__device__ __forceinline__ void phase5(const float* __restrict__ v,
                                       const float* __restrict__ D,
                                       float* __restrict__ arow,
                                       float* __restrict__ trow, int tid)
{
    #pragma unroll
    for (int i = 0; i < NGRP; ++i) {
        int t4 = 4 * (tid + i * THREADS);
        int p = padi(t4);
        float a0 = D[p], a1 = D[p + 1], a2 = D[p + 2], a3 = D[p + 3];
        float w0, w1, w2, w3;                       // v[t4 .. t4+3]
        if (t4 == 0 || t4 == T_CONST - 4) {
            w0 = __ldg(v + t4);     w1 = __ldg(v + t4 + 1);
            w2 = __ldg(v + t4 + 2); w3 = __ldg(v + t4 + 3);
        } else {
            float4 lo = __ldg(reinterpret_cast<const float4*>(v + t4 - O));
            if constexpr (O == 0) {
                w0 = lo.x; w1 = lo.y; w2 = lo.z; w3 = lo.w;
            } else {
                float4 hi = __ldg(reinterpret_cast<const float4*>(v + t4 - O + 4));
                float w[8] = {lo.x, lo.y, lo.z, lo.w, hi.x, hi.y, hi.z, hi.w};
                w0 = w[O]; w1 = w[O + 1]; w2 = w[O + 2]; w3 = w[O + 3];
            }
        }
        *reinterpret_cast<float4*>(arow + t4) = make_float4(a0, a1, a2, a3);
        *reinterpret_cast<float4*>(trow + t4) =
            make_float4(w0 + a0, w1 + a1, w2 + a2, w3 + a3);
    }
}

__global__ __launch_bounds__(THREADS, 2)
void gae_kernel(const float* __restrict__ rewards,
                const float* __restrict__ values,
                float* __restrict__ adv_out,
                float* __restrict__ tgt_out)
{
    extern __shared__ float D[];          // TPAD floats: deltas -> advantages
    __shared__ float wa[NWARP];
    __shared__ float wm[NWARP];
    __shared__ float wcarry[NWARP];

    const int row  = blockIdx.x;
    const int tid  = threadIdx.x;
    const int lane = tid & 31;
    const int wid  = tid >> 5;
    const float* r = rewards + (size_t)row * T_CONST;
    const float* v = values  + (size_t)row * (T_CONST + 1);
    const int O = row & 3;                // (row*8193 + t - O) % 4 == 0

    // ── Phase 1
    switch (O) {
        case 0: phase1<0>(r, v, D, tid); break;
        case 1: phase1<1>(r, v, D, tid); break;
        case 2: phase1<2>(r, v, D, tid); break;
        default: phase1<3>(r, v, D, tid); break;
    }
    __syncthreads();

    // ── Phase 2: per-thread local reverse scan of contiguous SEG=8 segment,
    // zero carry -> affine summary (a, m = COEF^8).
    const int base = tid * SEG;
    float a = 0.0f;
    #pragma unroll
    for (int k = SEG - 1; k >= 0; --k)
        a = D[padi(base + k)] + COEF * a;

    float m = COEF;                        // COEF^8 via 3 squarings
    m *= m; m *= m; m *= m;

    // ── Phase 3a: warp-level REVERSE inclusive scan of affine maps.
    #pragma unroll
    for (int d = 1; d < 32; d <<= 1) {
        float a2 = __shfl_down_sync(0xffffffffu, a, d);
        float m2 = __shfl_down_sync(0xffffffffu, m, d);
        if (lane + d < 32) { a = a + m * a2; m = m * m2; }
    }
    if (lane == 0) { wa[wid] = a; wm[wid] = m; }
    __syncthreads();

    // ── Phase 3b: warp 0 scans the 32 warp summaries -> per-warp carries.
    if (wid == 0) {
        float A = wa[lane], M = wm[lane];
        #pragma unroll
        for (int d = 1; d < 32; d <<= 1) {
            float A2 = __shfl_down_sync(0xffffffffu, A, d);
            float M2 = __shfl_down_sync(0xffffffffu, M, d);
            if (lane + d < 32) { A = A + M * A2; M = M * M2; }
        }
        float c = __shfl_down_sync(0xffffffffu, A, 1);
        wcarry[lane] = (lane == 31) ? 0.0f : c;
    }
    __syncthreads();

    // ── Carry entering this thread's segment.
    const float carryW = wcarry[wid];
    float an = __shfl_down_sync(0xffffffffu, a, 1);
    float mn = __shfl_down_sync(0xffffffffu, m, 1);
    const float carry = (lane == 31) ? carryW : an + mn * carryW;

    // ── Phase 4: exact sequential recurrence within segment, seeded w/ carry.
    float acc = carry;
    #pragma unroll
    for (int k = SEG - 1; k >= 0; --k) {
        int p = padi(base + k);
        acc = D[p] + COEF * acc;
        D[p] = acc;                        // delta -> advantage
    }
    __syncthreads();

    // ── Phase 5
    float* arow = adv_out + (size_t)row * T_CONST;
    float* trow = tgt_out + (size_t)row * T_CONST;
    switch (O) {
        case 0: phase5<0>(v, D, arow, trow, tid); break;
        case 1: phase5<1>(v, D, arow, trow, tid); break;
        case 2: phase5<2>(v, D, arow, trow, tid); break;
        default: phase5<3>(v, D, arow, trow, tid); break;
    }
}

extern "C" void kernel_launch(void* const* d_in, const int* in_sizes, int n_in,
                              void* d_out, int out_size)
{
    const float* rewards = (const float*)d_in[0];   // [B, T]
    const float* values  = (const float*)d_in[1];   // [B, T+1]
    float* adv = (float*)d_out;                     // [B, T]
    float* tgt = adv + (size_t)B_CONST * T_CONST;   // [B, T]

    const int smem_bytes = TPAD * (int)sizeof(float);  // ~33 KB
    cudaFuncSetAttribute(gae_kernel, cudaFuncAttributeMaxDynamicSharedMemorySize, smem_bytes);

    gae_kernel<<<B_CONST, THREADS, smem_bytes>>>(rewards, values, adv, tgt);
}

// round 6
// speedup vs baseline: 1.1562x; 1.1562x over previous
#include <cuda_runtime.h>

// GAE: advantages/targets, B=4096 rows, T=8192 timesteps.
// delta_t = r_t + GAMMA * v_{t+1} - v_t
// A_t = delta_t + COEF * A_{t+1}   (reverse scan, COEF = GAMMA*LAMBDA)
// targets_t = v_t + A_t
// Output layout: [advantages (B*T) | targets (B*T)] float32.
//
// R6: register-resident. Warp w in iteration i owns 32 contiguous timesteps;
// reverse affine scan per chunk via shuffles with CONSTANT multipliers
// (uniform-coefficient trick: a += COEF^d * shfl_down(a,d)). 256 chunk
// summaries scanned in ~2KB smem; carries applied at output as
// A = s[i] + COEF^(32-lane) * carry. No smem data array, 3 barriers total.

constexpr int   B_CONST  = 4096;
constexpr int   T_CONST  = 8192;
constexpr float GAMMA    = 0.99f;
constexpr float COEF     = 0.99f * 0.95f;        // gamma*lambda
constexpr int   THREADS  = 512;
constexpr int   NWARP    = THREADS / 32;         // 16
constexpr int   NITER    = T_CONST / THREADS;    // 16
constexpr int   NCHUNK   = NITER * NWARP;        // 256 chunks of 32 steps

__device__ __forceinline__ float powi_coef(float base, int n) {
    // base^n, n in [0,32], exact binary powering
    float r = 1.0f, b = base;
    #pragma unroll
    for (int bit = 0; bit < 6; ++bit) {
        if (n & (1 << bit)) r *= b;
        b *= b;
    }
    return r;
}

__global__ __launch_bounds__(THREADS, 3)
void gae_kernel(const float* __restrict__ rewards,
                const float* __restrict__ values,
                float* __restrict__ adv_out,
                float* __restrict__ tgt_out)
{
    __shared__ float sum[NCHUNK];    // chunk summaries (a); m uniform = COEF^32
    __shared__ float csum[NCHUNK];   // carry entering each chunk (scan of later chunks)
    __shared__ float wsum[NWARP / 2];    // 8 summary-warp aggregates
    __shared__ float wcar[NWARP / 2];    // 8 summary-warp carries

    const int row  = blockIdx.x;
    const int tid  = threadIdx.x;
    const int lane = tid & 31;
    const int wid  = tid >> 5;
    const float* r = rewards + (size_t)row * T_CONST;
    const float* v = values  + (size_t)row * (T_CONST + 1);

    // scan-step constants COEF^d, d = 1,2,4,8,16 (compile-time)
    const float C1  = COEF;
    const float C2  = C1 * C1;
    const float C4  = C2 * C2;
    const float C8  = C4 * C4;
    const float C16 = C8 * C8;
    const float M32 = C16 * C16;                 // COEF^32
    const float mlane = powi_coef(COEF, 32 - lane);

    // ── Phase 1: coalesced load + per-chunk (32 contiguous steps) shuffle scan.
    // s[i] = inclusive reverse scan value at this lane within chunk (zero carry).
    float s[NITER];
    #pragma unroll
    for (int i = 0; i < NITER; ++i) {
        int t = tid + i * THREADS;
        float vt = __ldg(v + t);
        float rt = __ldg(r + t);
        float vt1 = __shfl_down_sync(0xffffffffu, vt, 1);
        if (lane == 31) vt1 = __ldg(v + t + 1);
        float a = rt + GAMMA * vt1 - vt;          // delta_t

        // reverse Kogge-Stone with constant multipliers
        float a2;
        a2 = __shfl_down_sync(0xffffffffu, a, 1);  if (lane <  31) a += C1  * a2;
        a2 = __shfl_down_sync(0xffffffffu, a, 2);  if (lane <  30) a += C2  * a2;
        a2 = __shfl_down_sync(0xffffffffu, a, 4);  if (lane <  28) a += C4  * a2;
        a2 = __shfl_down_sync(0xffffffffu, a, 8);  if (lane <  24) a += C8  * a2;
        a2 = __shfl_down_sync(0xffffffffu, a, 16); if (lane <  16) a += C16 * a2;

        s[i] = a;
        if (lane == 0) sum[i * NWARP + wid] = a;  // chunk summary
    }
    __syncthreads();

    // ── Phase 2: scan 256 chunk summaries (uniform multiplier M32).
    // Level 1: threads 0..255 (8 warps), constant-multiplier warp scan.
    float sa = 0.0f;
    if (tid < NCHUNK) {
        sa = sum[tid];
        float k = M32, a2;
        a2 = __shfl_down_sync(0xffffffffu, sa, 1);  if (lane < 31) sa += k * a2;  k *= k;
        a2 = __shfl_down_sync(0xffffffffu, sa, 2);  if (lane < 30) sa += k * a2;  k *= k;
        a2 = __shfl_down_sync(0xffffffffu, sa, 4);  if (lane < 28) sa += k * a2;  k *= k;
        a2 = __shfl_down_sync(0xffffffffu, sa, 8);  if (lane < 24) sa += k * a2;  k *= k;
        a2 = __shfl_down_sync(0xffffffffu, sa, 16); if (lane < 16) sa += k * a2;
        if (lane == 0) wsum[wid] = sa;            // covers 32 chunks, m = M32^32
    }
    __syncthreads();

    // Level 2: warp 0 scans the 8 aggregates (uniform multiplier M32^32).
    if (wid == 0 && lane < 8) {
        float A = wsum[lane];
        float K = powi_coef(M32, 32);             // COEF^1024 (likely denormal->0; harmless)
        float a2;
        a2 = __shfl_down_sync(0x000000ffu, A, 1, 8); if (lane < 7) A += K * a2; K *= K;
        a2 = __shfl_down_sync(0x000000ffu, A, 2, 8); if (lane < 6) A += K * a2; K *= K;
        a2 = __shfl_down_sync(0x000000ffu, A, 4, 8); if (lane < 4) A += K * a2;
        float c = __shfl_down_sync(0x000000ffu, A, 1, 8);
        wcar[lane] = (lane == 7) ? 0.0f : c;      // carry entering summary-warp lane
    }
    __syncthreads();

    // csum[c] = carry entering chunk c = scan value at chunk c+1
    if (tid < NCHUNK) {
        float an = __shfl_down_sync(0xffffffffu, sa, 1);
        float wc = wcar[wid];
        float mnext = powi_coef(M32, 31 - lane);  // m of scan value at lane+1
        csum[tid] = (lane == 31) ? wc : an + mnext * wc;
    }
    __syncthreads();

    // ── Phase 3: apply carries, coalesced output; v re-read hits L1/L2.
    float* arow = adv_out + (size_t)row * T_CONST;
    float* trow = tgt_out + (size_t)row * T_CONST;
    #pragma unroll
    for (int i = 0; i < NITER; ++i) {
        int t = tid + i * THREADS;
        float carry = csum[i * NWARP + wid];      // broadcast within warp
        float A = fmaf(mlane, carry, s[i]);
        float vt = __ldg(v + t);
        arow[t] = A;
        trow[t] = vt + A;
    }
}

extern "C" void kernel_launch(void* const* d_in, const int* in_sizes, int n_in,
                              void* d_out, int out_size)
{
    const float* rewards = (const float*)d_in[0];   // [B, T]
    const float* values  = (const float*)d_in[1];   // [B, T+1]
    float* adv = (float*)d_out;                     // [B, T]
    float* tgt = adv + (size_t)B_CONST * T_CONST;   // [B, T]

    gae_kernel<<<B_CONST, THREADS>>>(rewards, values, adv, tgt);
}

// round 7
// speedup vs baseline: 1.4210x; 1.2290x over previous
#include <cuda_runtime.h>

// GAE: advantages/targets, B=4096 rows, T=8192 timesteps.
// delta_t = r_t + GAMMA*v_{t+1} - v_t ; A_t = delta_t + COEF*A_{t+1}
// targets_t = v_t + A_t. Output: [advantages | targets] float32.
//
// R7: truncated-window parallel GAE. COEF^512 ~ 2e-14, so each 4096-chunk is
// computed independently with a 512-element halo (error <<< 1e-3 tolerance).
// 2 CTAs/row, 512 thr, 8 main elems + 1 halo elem per thread -> 32 regs,
// 4 CTAs/SM. Quad-register layout: LDG.128/STG.128 everywhere (values
// realigned via compile-time O = row%4 template). Constant-multiplier
// shuffle scans; warp0 scans 48 chunk summaries; 2 barriers total.

constexpr int   B_CONST = 4096;
constexpr int   T_CONST = 8192;
constexpr float GAMMA   = 0.99f;
constexpr float COEF    = 0.99f * 0.95f;
constexpr int   THREADS = 512;
constexpr int   CHUNK   = 4096;                 // per-CTA main window
constexpr int   NITER   = CHUNK / (4 * THREADS);// 2 quad iterations
constexpr int   NMAIN   = 32;                   // 128-elem warp-chunks per CTA
constexpr int   NHALO   = 16;                   // 32-elem halo warp-chunks

__device__ __forceinline__ float powi_coef(float base, int n) {
    float r = 1.0f, b = base;
    #pragma unroll
    for (int bit = 0; bit < 7; ++bit) {        // n < 128
        if (n & (1 << bit)) r *= b;
        b *= b;
    }
    return r;
}

// scan constants
#define C1  (COEF)
#define C2  (C1*C1)
#define C3  (C2*C1)
#define C4  (C2*C2)
#define C8  (C4*C4)
#define C16 (C8*C8)
#define C32 (C16*C16)
#define C64 (C32*C32)
#define M32  C32
#define M128 (C64*C64)

template<int O>
__device__ __forceinline__ void gae_body(const float* __restrict__ r_row,
                                         const float* __restrict__ v_row,
                                         float* __restrict__ arow,
                                         float* __restrict__ trow,
                                         int cbase,
                                         float* __restrict__ sum,    // [48]
                                         float* __restrict__ csum)   // [32]
{
    const int tid  = threadIdx.x;
    const int lane = tid & 31;
    const int wid  = tid >> 5;

    float s0[NITER], s1[NITER], s2[NITER], s3[NITER];

    // ── Phase 1: main quads. Load, delta, quad scan, warp scan (mult C4^d).
    #pragma unroll
    for (int i = 0; i < NITER; ++i) {
        const int t4 = cbase + 4 * (tid + i * THREADS);
        // v[t4..t4+4] from two aligned float4s (window select is compile-time)
        float4 lo = __ldg(reinterpret_cast<const float4*>(v_row + t4 - O));
        float4 hi = __ldg(reinterpret_cast<const float4*>(v_row + t4 - O + 4));
        float w[8] = {lo.x, lo.y, lo.z, lo.w, hi.x, hi.y, hi.z, hi.w};
        float4 r4 = __ldg(reinterpret_cast<const float4*>(r_row + t4));

        float d0 = r4.x + GAMMA * w[O + 1] - w[O];
        float d1 = r4.y + GAMMA * w[O + 2] - w[O + 1];
        float d2 = r4.z + GAMMA * w[O + 3] - w[O + 2];
        float d3 = r4.w + GAMMA * w[O + 4] - w[O + 3];

        // reverse scan within quad (zero carry)
        float q3 = d3;
        float q2 = fmaf(C1, q3, d2);
        float q1 = fmaf(C1, q2, d1);
        float q0 = fmaf(C1, q1, d0);

        // warp reverse scan of quad summaries, multiplier C4 per step
        float S = q0, a2;
        a2 = __shfl_down_sync(0xffffffffu, S, 1);  if (lane < 31) S = fmaf(C4,  a2, S);
        a2 = __shfl_down_sync(0xffffffffu, S, 2);  if (lane < 30) S = fmaf(C8,  a2, S);
        a2 = __shfl_down_sync(0xffffffffu, S, 4);  if (lane < 28) S = fmaf(C16, a2, S);
        a2 = __shfl_down_sync(0xffffffffu, S, 8);  if (lane < 24) S = fmaf(C32, a2, S);
        a2 = __shfl_down_sync(0xffffffffu, S, 16); if (lane < 16) S = fmaf(C64, a2, S);

        float E = __shfl_down_sync(0xffffffffu, S, 1);   // carry into this quad
        if (lane == 31) E = 0.0f;

        s0[i] = fmaf(C4, E, q0);
        s1[i] = fmaf(C3, E, q1);
        s2[i] = fmaf(C2, E, q2);
        s3[i] = fmaf(C1, E, q3);
        if (lane == 0) sum[i * 16 + wid] = S;    // 128-elem chunk summary
    }

    // ── Halo pass: 512 scalar elements beyond the chunk (guarded at row end).
    {
        const int t = cbase + CHUNK + tid;
        const bool inb = (t < T_CONST);
        float vt  = inb ? __ldg(v_row + t)     : 0.0f;
        float vt1 = inb ? __ldg(v_row + t + 1) : 0.0f;
        float rt  = inb ? __ldg(r_row + t)     : 0.0f;
        float a = inb ? (rt + GAMMA * vt1 - vt) : 0.0f;
        float a2;
        a2 = __shfl_down_sync(0xffffffffu, a, 1);  if (lane < 31) a = fmaf(C1,  a2, a);
        a2 = __shfl_down_sync(0xffffffffu, a, 2);  if (lane < 30) a = fmaf(C2,  a2, a);
        a2 = __shfl_down_sync(0xffffffffu, a, 4);  if (lane < 28) a = fmaf(C4,  a2, a);
        a2 = __shfl_down_sync(0xffffffffu, a, 8);  if (lane < 24) a = fmaf(C8,  a2, a);
        a2 = __shfl_down_sync(0xffffffffu, a, 16); if (lane < 16) a = fmaf(C16, a2, a);
        if (lane == 0) sum[NMAIN + wid] = a;     // 32-elem halo chunk summary
    }
    __syncthreads();

    // ── Phase 2 (warp 0 only): scan 16 halo summaries (mult M32), then 32
    // main summaries (mult M128); fold halo total in analytically.
    if (wid == 0) {
        // halo total T1: scan over 16 (lanes >=16 hold 0, harmless)
        float A = (lane < NHALO) ? sum[NMAIN + lane] : 0.0f;
        float a2, k = M32;
        a2 = __shfl_down_sync(0xffffffffu, A, 1);  if (lane < 31) A = fmaf(k, a2, A); k *= k;
        a2 = __shfl_down_sync(0xffffffffu, A, 2);  if (lane < 30) A = fmaf(k, a2, A); k *= k;
        a2 = __shfl_down_sync(0xffffffffu, A, 4);  if (lane < 28) A = fmaf(k, a2, A); k *= k;
        a2 = __shfl_down_sync(0xffffffffu, A, 8);  if (lane < 24) A = fmaf(k, a2, A);
        float T1 = __shfl_sync(0xffffffffu, A, 0);

        // main scan (zero carry), uniform multiplier M128
        float S = sum[lane];
        k = M128;
        a2 = __shfl_down_sync(0xffffffffu, S, 1);  if (lane < 31) S = fmaf(k, a2, S); k *= k;
        a2 = __shfl_down_sync(0xffffffffu, S, 2);  if (lane < 30) S = fmaf(k, a2, S); k *= k;
        a2 = __shfl_down_sync(0xffffffffu, S, 4);  if (lane < 28) S = fmaf(k, a2, S); k *= k;
        a2 = __shfl_down_sync(0xffffffffu, S, 8);  if (lane < 24) S = fmaf(k, a2, S); k *= k;
        a2 = __shfl_down_sync(0xffffffffu, S, 16); if (lane < 16) S = fmaf(k, a2, S);

        // carry entering chunk c: G_{c+1} = S_{c+1} + M128^(31-c) * T1
        float Sn   = __shfl_down_sync(0xffffffffu, S, 1);
        float corr = powi_coef(M128, 31 - lane);          // underflows to 0 fast: fine
        csum[lane] = (lane == 31) ? T1 : fmaf(corr, T1, Sn);
    }
    __syncthreads();

    // ── Phase 3: apply carries, reload v (L1-resident), vector stores.
    float m3 = powi_coef(COEF, 125 - 4 * lane);           // COEF^(125-4l)
    float m2 = m3 * C1, m1 = m2 * C1, m0 = m1 * C1;       // .. up to COEF^(128-4l)

    #pragma unroll
    for (int i = 0; i < NITER; ++i) {
        const int t4 = cbase + 4 * (tid + i * THREADS);
        const float carry = csum[i * 16 + wid];           // broadcast in warp
        float A0 = fmaf(m0, carry, s0[i]);
        float A1 = fmaf(m1, carry, s1[i]);
        float A2 = fmaf(m2, carry, s2[i]);
        float A3 = fmaf(m3, carry, s3[i]);

        float w0, w1, w2, w3;
        {
            float4 lo = __ldg(reinterpret_cast<const float4*>(v_row + t4 - O));
            if constexpr (O == 0) {
                w0 = lo.x; w1 = lo.y; w2 = lo.z; w3 = lo.w;
            } else {
                float4 hi = __ldg(reinterpret_cast<const float4*>(v_row + t4 - O + 4));
                float w[8] = {lo.x, lo.y, lo.z, lo.w, hi.x, hi.y, hi.z, hi.w};
                w0 = w[O]; w1 = w[O + 1]; w2 = w[O + 2]; w3 = w[O + 3];
            }
        }
        *reinterpret_cast<float4*>(arow + t4) = make_float4(A0, A1, A2, A3);
        *reinterpret_cast<float4*>(trow + t4) =
            make_float4(w0 + A0, w1 + A1, w2 + A2, w3 + A3);
    }
}

__global__ __launch_bounds__(THREADS, 4)
void gae_kernel(const float* __restrict__ rewards,
                const float* __restrict__ values,
                float* __restrict__ adv_out,
                float* __restrict__ tgt_out)
{
    __shared__ float sum[NMAIN + NHALO];   // 48 chunk summaries
    __shared__ float csum[NMAIN];          // carries for main chunks

    const int row   = blockIdx.x >> 1;
    const int half  = blockIdx.x & 1;
    const int cbase = half * CHUNK;

    const float* r_row = rewards + (size_t)row * T_CONST;
    const float* v_row = values  + (size_t)row * (T_CONST + 1);
    float* arow = adv_out + (size_t)row * T_CONST;
    float* trow = tgt_out + (size_t)row * T_CONST;

    // values row misalignment: (row*8193 + t) % 4 == (row + t) % 4.
    // Row 4095 (the only row where tail vector loads could run past the
    // buffer) has O = 3, which keeps the max touched index at v[T]. Safe.
    switch (row & 3) {
        case 0:  gae_body<0>(r_row, v_row, arow, trow, cbase, sum, csum); break;
        case 1:  gae_body<1>(r_row, v_row, arow, trow, cbase, sum, csum); break;
        case 2:  gae_body<2>(r_row, v_row, arow, trow, cbase, sum, csum); break;
        default: gae_body<3>(r_row, v_row, arow, trow, cbase, sum, csum); break;
    }
}

extern "C" void kernel_launch(void* const* d_in, const int* in_sizes, int n_in,
                              void* d_out, int out_size)
{
    const float* rewards = (const float*)d_in[0];   // [B, T]
    const float* values  = (const float*)d_in[1];   // [B, T+1]
    float* adv = (float*)d_out;                     // [B, T]
    float* tgt = adv + (size_t)B_CONST * T_CONST;   // [B, T]

    gae_kernel<<<B_CONST * 2, THREADS>>>(rewards, values, adv, tgt);
}